// round 5
// baseline (speedup 1.0000x reference)
#include <cuda_runtime.h>
#include <cuda_bf16.h>
#include <cstdint>

// Problem constants
#define B_   1024
#define T_   128
#define OBS_ 256
#define LAT_ 64
#define BT_  (B_ * T_)   // 131072
#define SEQ_GRID 148
#define SROW 40          // padded smem row (bf16): conflict-free frag loads

// ---------------------------------------------------------------------------
// Static device scratch (allocation-free rule)
// ---------------------------------------------------------------------------
__device__ __nv_bfloat16 g_bufA_hi[(size_t)BT_ * 512];
__device__ __nv_bfloat16 g_bufA_lo[(size_t)BT_ * 512];
__device__ __nv_bfloat16 g_bufB_hi[(size_t)BT_ * 512];
__device__ __nv_bfloat16 g_bufB_lo[(size_t)BT_ * 512];
__device__ float         g_posc[(size_t)BT_ * 512];     // pos-contrib (fp32)
__device__ __nv_bfloat16 g_z_hi[(size_t)BT_ * 64];
__device__ __nv_bfloat16 g_z_lo[(size_t)BT_ * 64];
__device__ __nv_bfloat16 g_act_hi[(size_t)B_ * 1024];   // S1 out: pri|pos
__device__ __nv_bfloat16 g_act_lo[(size_t)B_ * 1024];
__device__ __nv_bfloat16 g_a1_hi[(size_t)B_ * 1024];    // S2 out
__device__ __nv_bfloat16 g_a1_lo[(size_t)B_ * 1024];
__device__ float         g_gh[(size_t)B_ * 1536];       // S1 gh out (fp32)
__device__ float         g_out2[(size_t)B_ * 256];      // S3 out
__device__ float         g_h[(size_t)B_ * 512];
__device__ __nv_bfloat16 g_h_hi[(size_t)B_ * 512];
__device__ __nv_bfloat16 g_h_lo[(size_t)B_ * 512];
__device__ float         g_wiht[64 * 1536];             // Wih^T fp32
__device__ unsigned      g_bar_cnt;                     // zero-init
__device__ volatile unsigned g_bar_flag;                // zero-init

// Packed bf16 hi/lo weights
enum : int {
    OFF_encW0  = 0,
    OFF_encW1  = OFF_encW0  + 512 * 256,
    OFF_encW2  = OFF_encW1  + 512 * 512,
    OFF_posW0e = OFF_encW2  + 512 * 512,
    OFF_posW0h = OFF_posW0e + 512 * 512,
    OFF_priW0  = OFF_posW0h + 512 * 512,
    OFF_gruWhh = OFF_priW0  + 512 * 512,
    OFF_priW1  = OFF_gruWhh + 1536 * 512,
    OFF_posW1  = OFF_priW1  + 512 * 512,
    OFF_priW2  = OFF_posW1  + 512 * 512,
    OFF_posW2  = OFF_priW2  + 128 * 512,
    OFF_decW0  = OFF_posW2  + 128 * 512,
    OFF_decW1  = OFF_decW0  + 512 * 64,
    OFF_decW2  = OFF_decW1  + 512 * 512,
    WTOT       = OFF_decW2  + 256 * 512
};
__device__ __nv_bfloat16 g_whi[WTOT];
__device__ __nv_bfloat16 g_wlo[WTOT];

__device__ __forceinline__ float eluf(float x) { return x > 0.f ? x : expm1f(x); }

// ---------------------------------------------------------------------------
// mma.sync bf16 (sm_80+ PTX — valid at plain compute_103)
// ---------------------------------------------------------------------------
__device__ __forceinline__ void mma_bf16(float* c, const uint32_t* a, uint32_t b0, uint32_t b1) {
    asm volatile(
        "mma.sync.aligned.m16n8k16.row.col.f32.bf16.bf16.f32 "
        "{%0,%1,%2,%3}, {%4,%5,%6,%7}, {%8,%9}, {%0,%1,%2,%3};"
        : "+f"(c[0]), "+f"(c[1]), "+f"(c[2]), "+f"(c[3])
        : "r"(a[0]), "r"(a[1]), "r"(a[2]), "r"(a[3]), "r"(b0), "r"(b1));
}

// ---------------------------------------------------------------------------
// Shared tile storage: 4 x 128 x SROW bf16 = 40,960 B
// ---------------------------------------------------------------------------
struct TileSmem {
    __nv_bfloat16 sAh[128 * SROW];
    __nv_bfloat16 sAl[128 * SROW];
    __nv_bfloat16 sWh[128 * SROW];
    __nv_bfloat16 sWl[128 * SROW];
};

// ---------------------------------------------------------------------------
// 128x128 tile GEMM core. APAIRS: A given as bf16 hi/lo; else fp32 (converted).
// W: bf16 hi/lo, K-major, pre-offset to tile's first row; ldw = K.
// bf16x3 emulation (ah*bh + ah*bl + al*bh), fp32 accum. 256 threads (8 warps).
// ---------------------------------------------------------------------------
template <bool APAIRS>
__device__ __forceinline__ void tile_gemm(
    TileSmem& S,
    const float* Af, const __nv_bfloat16* Ahi, const __nv_bfloat16* Alo, int lda,
    const __nv_bfloat16* Whi, const __nv_bfloat16* Wlo,
    int K, int m0, float acc[4][4][4])
{
    const int tid = threadIdx.x;
    const int wid = tid >> 5;
    const int lane = tid & 31;
    const int gid = lane >> 2;
    const int tig = lane & 3;
    const int warp_m = wid & 1;
    const int warp_n = wid >> 1;
    const int NC = K >> 5;

#pragma unroll
    for (int i = 0; i < 4; i++)
#pragma unroll
        for (int j = 0; j < 4; j++)
#pragma unroll
            for (int q = 0; q < 4; q++) acc[i][j][q] = 0.f;

    float av[16];
    uint4 pah[2], pal[2], pwh[2], pwl[2];

    auto load_g = [&](int kc) {
        const int k0 = kc << 5;
        if (APAIRS) {
#pragma unroll
            for (int i = 0; i < 2; i++) {
                const int idx = tid + i * 256;
                const int row = idx >> 2, col = (idx & 3) * 8;
                pah[i] = *reinterpret_cast<const uint4*>(Ahi + (size_t)(m0 + row) * lda + k0 + col);
                pal[i] = *reinterpret_cast<const uint4*>(Alo + (size_t)(m0 + row) * lda + k0 + col);
            }
        } else {
#pragma unroll
            for (int i = 0; i < 4; i++) {
                const int idx = tid + i * 256;
                const int row = idx >> 3, col = (idx & 7) * 4;
                const float4 v = *reinterpret_cast<const float4*>(
                    Af + (size_t)(m0 + row) * lda + k0 + col);
                av[i * 4 + 0] = v.x; av[i * 4 + 1] = v.y;
                av[i * 4 + 2] = v.z; av[i * 4 + 3] = v.w;
            }
        }
#pragma unroll
        for (int i = 0; i < 2; i++) {
            const int idx = tid + i * 256;
            const int row = idx >> 2, col = (idx & 3) * 8;
            pwh[i] = *reinterpret_cast<const uint4*>(Whi + (size_t)row * K + k0 + col);
            pwl[i] = *reinterpret_cast<const uint4*>(Wlo + (size_t)row * K + k0 + col);
        }
    };

    auto stage = [&]() {
        if (APAIRS) {
#pragma unroll
            for (int i = 0; i < 2; i++) {
                const int idx = tid + i * 256;
                const int row = idx >> 2, col = (idx & 3) * 8;
                *reinterpret_cast<uint4*>(&S.sAh[row * SROW + col]) = pah[i];
                *reinterpret_cast<uint4*>(&S.sAl[row * SROW + col]) = pal[i];
            }
        } else {
#pragma unroll
            for (int i = 0; i < 4; i++) {
                const int idx = tid + i * 256;
                const int row = idx >> 3, col = (idx & 7) * 4;
                float x0 = av[i * 4 + 0], x1 = av[i * 4 + 1];
                float x2 = av[i * 4 + 2], x3 = av[i * 4 + 3];
                __nv_bfloat162 h01 = __floats2bfloat162_rn(x0, x1);
                __nv_bfloat162 h23 = __floats2bfloat162_rn(x2, x3);
                __nv_bfloat162 l01 = __floats2bfloat162_rn(x0 - __bfloat162float(h01.x),
                                                           x1 - __bfloat162float(h01.y));
                __nv_bfloat162 l23 = __floats2bfloat162_rn(x2 - __bfloat162float(h23.x),
                                                           x3 - __bfloat162float(h23.y));
                const int so = row * SROW + col;
                *reinterpret_cast<uint32_t*>(&S.sAh[so])     = *reinterpret_cast<uint32_t*>(&h01);
                *reinterpret_cast<uint32_t*>(&S.sAh[so + 2]) = *reinterpret_cast<uint32_t*>(&h23);
                *reinterpret_cast<uint32_t*>(&S.sAl[so])     = *reinterpret_cast<uint32_t*>(&l01);
                *reinterpret_cast<uint32_t*>(&S.sAl[so + 2]) = *reinterpret_cast<uint32_t*>(&l23);
            }
        }
#pragma unroll
        for (int i = 0; i < 2; i++) {
            const int idx = tid + i * 256;
            const int row = idx >> 2, col = (idx & 3) * 8;
            *reinterpret_cast<uint4*>(&S.sWh[row * SROW + col]) = pwh[i];
            *reinterpret_cast<uint4*>(&S.sWl[row * SROW + col]) = pwl[i];
        }
    };

    load_g(0);
    for (int kc = 0; kc < NC; kc++) {
        stage();
        __syncthreads();
        if (kc + 1 < NC) load_g(kc + 1);

#pragma unroll
        for (int ks = 0; ks < 32; ks += 16) {
            uint32_t ah[4][4], al[4][4];
            const int kk = ks + tig * 2;
#pragma unroll
            for (int mf = 0; mf < 4; mf++) {
                const int r0 = warp_m * 64 + mf * 16 + gid;
                ah[mf][0] = *reinterpret_cast<const uint32_t*>(&S.sAh[r0 * SROW + kk]);
                ah[mf][1] = *reinterpret_cast<const uint32_t*>(&S.sAh[(r0 + 8) * SROW + kk]);
                ah[mf][2] = *reinterpret_cast<const uint32_t*>(&S.sAh[r0 * SROW + kk + 8]);
                ah[mf][3] = *reinterpret_cast<const uint32_t*>(&S.sAh[(r0 + 8) * SROW + kk + 8]);
                al[mf][0] = *reinterpret_cast<const uint32_t*>(&S.sAl[r0 * SROW + kk]);
                al[mf][1] = *reinterpret_cast<const uint32_t*>(&S.sAl[(r0 + 8) * SROW + kk]);
                al[mf][2] = *reinterpret_cast<const uint32_t*>(&S.sAl[r0 * SROW + kk + 8]);
                al[mf][3] = *reinterpret_cast<const uint32_t*>(&S.sAl[(r0 + 8) * SROW + kk + 8]);
            }
#pragma unroll
            for (int nf = 0; nf < 4; nf++) {
                const int c0 = warp_n * 32 + nf * 8 + gid;
                const uint32_t bh0 = *reinterpret_cast<const uint32_t*>(&S.sWh[c0 * SROW + kk]);
                const uint32_t bh1 = *reinterpret_cast<const uint32_t*>(&S.sWh[c0 * SROW + kk + 8]);
                const uint32_t bl0 = *reinterpret_cast<const uint32_t*>(&S.sWl[c0 * SROW + kk]);
                const uint32_t bl1 = *reinterpret_cast<const uint32_t*>(&S.sWl[c0 * SROW + kk + 8]);
#pragma unroll
                for (int mf = 0; mf < 4; mf++) {
                    mma_bf16(acc[mf][nf], ah[mf], bh0, bh1);
                    mma_bf16(acc[mf][nf], ah[mf], bl0, bl1);
                    mma_bf16(acc[mf][nf], al[mf], bh0, bh1);
                }
            }
        }
        __syncthreads();
    }
}

// Epilogue: bias/add/ELU; mode 0 = fp32 C, mode 1 = bf16 hi/lo pairs.
// All pointers pre-offset to the tile's first column; ld* are row strides.
__device__ __forceinline__ void tile_epilogue(
    float acc[4][4][4],
    const float* bias, const float* add, long ldadd, int act,
    int mode, float* C, __nv_bfloat16* Chi, __nv_bfloat16* Clo, int ldc, int m0)
{
    const int tid = threadIdx.x;
    const int wid = tid >> 5;
    const int lane = tid & 31;
    const int gid = lane >> 2;
    const int tig = lane & 3;
    const int warp_m = wid & 1;
    const int warp_n = wid >> 1;

#pragma unroll
    for (int mf = 0; mf < 4; mf++) {
        const int r0 = m0 + warp_m * 64 + mf * 16 + gid;
#pragma unroll
        for (int nf = 0; nf < 4; nf++) {
            const int coll = warp_n * 32 + nf * 8 + tig * 2;
            float v0 = acc[mf][nf][0], v1 = acc[mf][nf][1];
            float v2 = acc[mf][nf][2], v3 = acc[mf][nf][3];
            if (bias) {
                const float b0v = bias[coll], b1v = bias[coll + 1];
                v0 += b0v; v1 += b1v; v2 += b0v; v3 += b1v;
            }
            if (add) {
                const float2 a0 = *reinterpret_cast<const float2*>(add + (size_t)r0 * ldadd + coll);
                const float2 a1 = *reinterpret_cast<const float2*>(add + (size_t)(r0 + 8) * ldadd + coll);
                v0 += a0.x; v1 += a0.y; v2 += a1.x; v3 += a1.y;
            }
            if (act) { v0 = eluf(v0); v1 = eluf(v1); v2 = eluf(v2); v3 = eluf(v3); }
            if (mode == 0) {
                *reinterpret_cast<float2*>(C + (size_t)r0 * ldc + coll)       = make_float2(v0, v1);
                *reinterpret_cast<float2*>(C + (size_t)(r0 + 8) * ldc + coll) = make_float2(v2, v3);
            } else {
                __nv_bfloat162 h0 = __floats2bfloat162_rn(v0, v1);
                __nv_bfloat162 l0 = __floats2bfloat162_rn(v0 - __bfloat162float(h0.x),
                                                          v1 - __bfloat162float(h0.y));
                __nv_bfloat162 h1 = __floats2bfloat162_rn(v2, v3);
                __nv_bfloat162 l1 = __floats2bfloat162_rn(v2 - __bfloat162float(h1.x),
                                                          v3 - __bfloat162float(h1.y));
                *reinterpret_cast<uint32_t*>(Chi + (size_t)r0 * ldc + coll)       = *reinterpret_cast<uint32_t*>(&h0);
                *reinterpret_cast<uint32_t*>(Clo + (size_t)r0 * ldc + coll)       = *reinterpret_cast<uint32_t*>(&l0);
                *reinterpret_cast<uint32_t*>(Chi + (size_t)(r0 + 8) * ldc + coll) = *reinterpret_cast<uint32_t*>(&h1);
                *reinterpret_cast<uint32_t*>(Clo + (size_t)(r0 + 8) * ldc + coll) = *reinterpret_cast<uint32_t*>(&l1);
            }
        }
    }
}

// ---------------------------------------------------------------------------
// Big (parallel-wide) GEMM kernel: single group, no add.
// ---------------------------------------------------------------------------
template <bool APAIRS>
__global__ void __launch_bounds__(256) gemm_big(
    const float* Af, const __nv_bfloat16* Ahi, const __nv_bfloat16* Alo, int lda,
    const __nv_bfloat16* Whi, const __nv_bfloat16* Wlo, int K,
    const float* bias, int act, int mode,
    float* C, __nv_bfloat16* Chi, __nv_bfloat16* Clo, int ldc)
{
    __shared__ TileSmem S;
    const int n0 = blockIdx.x * 128;
    const int m0 = blockIdx.y * 128;
    float acc[4][4][4];
    tile_gemm<APAIRS>(S, Af, Ahi, Alo, lda,
                      Whi + (size_t)n0 * K, Wlo + (size_t)n0 * K, K, m0, acc);
    tile_epilogue(acc, bias ? bias + n0 : nullptr, nullptr, 0, act, mode,
                  C ? C + n0 : nullptr,
                  Chi ? Chi + n0 : nullptr, Clo ? Clo + n0 : nullptr, ldc, m0);
}

// ---------------------------------------------------------------------------
// Persistent sequential kernel: all 128 timesteps, software grid barrier.
// ---------------------------------------------------------------------------
struct SeqArgs {
    const float* eps;
    const float* bih;
    const float* pri_b0;
    const float* bhh;
    const float* pri_b1;
    const float* pos_b1;
    const float* pri_b2;
    const float* pos_b2;
    float* kls;
    float* mu;
};

__device__ __forceinline__ void grid_bar(int& sense) {
    __syncthreads();
    if (threadIdx.x == 0) {
        __threadfence();
        const unsigned G = gridDim.x;
        unsigned old = atomicAdd(&g_bar_cnt, 1u);
        if (old == G - 1) {
            atomicExch(&g_bar_cnt, 0u);
            __threadfence();
            g_bar_flag = (unsigned)sense;
        } else {
            while (g_bar_flag != (unsigned)sense) { }
            __threadfence();
        }
    }
    __syncthreads();
    sense ^= 1;
}

__global__ void __launch_bounds__(256, 1) seq_kernel(SeqArgs a) {
    __shared__ TileSmem S;
    __shared__ float zsh[7][64];
    __shared__ float klp[7][2];

    const int cta = blockIdx.x;
    const int G = gridDim.x;
    const int tid = threadIdx.x;
    const int wid = tid >> 5;
    const int lane = tid & 31;
    int sense = 1;

#pragma unroll 1
    for (int t = 0; t < T_; t++) {
        // ---- S1: h -> [pri_a0 | pos_a0 | gh]  (160 tiles of 128x128, K=512)
        for (int tile = cta; tile < 160; tile += G) {
            const int m0 = (tile / 20) * 128;
            const int nt = tile % 20;
            float acc[4][4][4];
            const __nv_bfloat16 *wh, *wl;
            const float* bias = nullptr; const float* add = nullptr; long ldadd = 0;
            int act, mode, ldc;
            float* Cf = nullptr; __nv_bfloat16 *ch = nullptr, *cl = nullptr;
            if (nt < 4) {
                wh = g_whi + OFF_priW0 + (size_t)nt * 128 * 512;
                wl = g_wlo + OFF_priW0 + (size_t)nt * 128 * 512;
                bias = a.pri_b0 + nt * 128; act = 1; mode = 1;
                ch = g_act_hi + nt * 128; cl = g_act_lo + nt * 128; ldc = 1024;
            } else if (nt < 8) {
                const int q = nt - 4;
                wh = g_whi + OFF_posW0h + (size_t)q * 128 * 512;
                wl = g_wlo + OFF_posW0h + (size_t)q * 128 * 512;
                add = g_posc + (size_t)t * 512 + q * 128; ldadd = (long)T_ * 512;
                act = 1; mode = 1;
                ch = g_act_hi + 512 + q * 128; cl = g_act_lo + 512 + q * 128; ldc = 1024;
            } else {
                const int q = nt - 8;
                wh = g_whi + OFF_gruWhh + (size_t)q * 128 * 512;
                wl = g_wlo + OFF_gruWhh + (size_t)q * 128 * 512;
                bias = a.bhh + q * 128; act = 0; mode = 0;
                Cf = g_gh + q * 128; ldc = 1536;
            }
            tile_gemm<true>(S, nullptr, g_h_hi, g_h_lo, 512, wh, wl, 512, m0, acc);
            tile_epilogue(acc, bias, add, ldadd, act, mode, Cf, ch, cl, ldc, m0);
        }
        grid_bar(sense);

        // ---- S2: [pri_a1 | pos_a1]  (64 tiles, K=512)
        for (int tile = cta; tile < 64; tile += G) {
            const int m0 = (tile / 8) * 128;
            const int nt = tile % 8;
            float acc[4][4][4];
            const __nv_bfloat16 *wh, *wl, *ahp, *alp;
            const float* bias;
            __nv_bfloat16 *ch, *cl;
            if (nt < 4) {
                ahp = g_act_hi; alp = g_act_lo;
                wh = g_whi + OFF_priW1 + (size_t)nt * 128 * 512;
                wl = g_wlo + OFF_priW1 + (size_t)nt * 128 * 512;
                bias = a.pri_b1 + nt * 128;
                ch = g_a1_hi + nt * 128; cl = g_a1_lo + nt * 128;
            } else {
                const int q = nt - 4;
                ahp = g_act_hi + 512; alp = g_act_lo + 512;
                wh = g_whi + OFF_posW1 + (size_t)q * 128 * 512;
                wl = g_wlo + OFF_posW1 + (size_t)q * 128 * 512;
                bias = a.pos_b1 + q * 128;
                ch = g_a1_hi + 512 + q * 128; cl = g_a1_lo + 512 + q * 128;
            }
            tile_gemm<true>(S, nullptr, ahp, alp, 1024, wh, wl, 512, m0, acc);
            tile_epilogue(acc, bias, nullptr, 0, 1, 1, nullptr, ch, cl, 1024, m0);
        }
        grid_bar(sense);

        // ---- S3: [pri2 | pos2]  (16 tiles, K=512)
        for (int tile = cta; tile < 16; tile += G) {
            const int m0 = (tile / 2) * 128;
            const int nt = tile % 2;
            float acc[4][4][4];
            const __nv_bfloat16* ahp = nt ? g_a1_hi + 512 : g_a1_hi;
            const __nv_bfloat16* alp = nt ? g_a1_lo + 512 : g_a1_lo;
            const __nv_bfloat16* wh = g_whi + (nt ? OFF_posW2 : OFF_priW2);
            const __nv_bfloat16* wl = g_wlo + (nt ? OFF_posW2 : OFF_priW2);
            const float* bias = nt ? a.pos_b2 : a.pri_b2;
            tile_gemm<true>(S, nullptr, ahp, alp, 1024, wh, wl, 512, m0, acc);
            tile_epilogue(acc, bias, nullptr, 0, 0, 0, g_out2 + nt * 128, nullptr, nullptr, 256, m0);
        }
        grid_bar(sense);

        // ---- Phase D: latent sample + kl + mu + GRU update (7 rows per CTA)
        {
            const int r0 = cta * 7;
            if (r0 < B_) {
                const int nr = min(7, B_ - r0);
                // z / kl / mu: 2 warps per row, two passes of 4 rows
#pragma unroll
                for (int p = 0; p < 2; p++) {
                    const int rr = p * 4 + (wid >> 1);
                    if (rr < nr) {
                        const int k = ((wid & 1) << 5) + lane;
                        const int m = r0 + rr;
                        const float* o = g_out2 + (size_t)m * 256;
                        const float mu_p = o[k], ls_p = o[64 + k];
                        const float mu_q = o[128 + k], ls_q = o[192 + k];
                        const float e = a.eps[((size_t)m * T_ + t) * 64 + k];
                        const float z = fmaf(expf(ls_q), e, mu_q);
                        zsh[rr][k] = z;
                        const __nv_bfloat16 zh = __float2bfloat16(z);
                        g_z_hi[((size_t)m * T_ + t) * 64 + k] = zh;
                        g_z_lo[((size_t)m * T_ + t) * 64 + k] =
                            __float2bfloat16(z - __bfloat162float(zh));
                        a.mu[((size_t)m * T_ + t) * 64 + k] = mu_q;
                        const float dm = mu_q - mu_p;
                        float klv = ls_p - ls_q +
                                    (expf(2.f * ls_q) + dm * dm) / (2.f * expf(2.f * ls_p)) - 0.5f;
#pragma unroll
                        for (int off = 16; off > 0; off >>= 1)
                            klv += __shfl_down_sync(0xffffffffu, klv, off);
                        if (lane == 0) klp[rr][wid & 1] = klv;
                    }
                }
                __syncthreads();
                if (tid < nr)
                    a.kls[(size_t)(r0 + tid) * T_ + t] = klp[tid][0] + klp[tid][1];

                // gates: each thread 2 cols (tid, tid+256)
#pragma unroll
                for (int jj = 0; jj < 2; jj++) {
                    const int j = tid + jj * 256;
                    float AR[7], AZ[7], AN[7];
#pragma unroll
                    for (int r = 0; r < 7; r++) { AR[r] = 0.f; AZ[r] = 0.f; AN[r] = 0.f; }
                    const float* wp = g_wiht + j;
#pragma unroll 4
                    for (int k = 0; k < 64; k++) {
                        const float wr = wp[k * 1536];
                        const float wz = wp[k * 1536 + 512];
                        const float wn = wp[k * 1536 + 1024];
#pragma unroll
                        for (int r = 0; r < 7; r++) {
                            const float zk = zsh[r][k];
                            AR[r] = fmaf(zk, wr, AR[r]);
                            AZ[r] = fmaf(zk, wz, AZ[r]);
                            AN[r] = fmaf(zk, wn, AN[r]);
                        }
                    }
                    const float br = a.bih[j], bz = a.bih[512 + j], bn = a.bih[1024 + j];
#pragma unroll
                    for (int r = 0; r < 7; r++) {
                        if (r < nr) {
                            const int m = r0 + r;
                            const float ghr = g_gh[(size_t)m * 1536 + j];
                            const float ghz = g_gh[(size_t)m * 1536 + 512 + j];
                            const float ghn = g_gh[(size_t)m * 1536 + 1024 + j];
                            const float rg = 1.f / (1.f + expf(-(AR[r] + br + ghr)));
                            const float zg = 1.f / (1.f + expf(-(AZ[r] + bz + ghz)));
                            const float ng = tanhf(AN[r] + bn + rg * ghn);
                            const float hv = g_h[(size_t)m * 512 + j];
                            const float hn = (1.f - zg) * ng + zg * hv;
                            g_h[(size_t)m * 512 + j] = hn;
                            const __nv_bfloat16 hh = __float2bfloat16(hn);
                            g_h_hi[(size_t)m * 512 + j] = hh;
                            g_h_lo[(size_t)m * 512 + j] =
                                __float2bfloat16(hn - __bfloat162float(hh));
                        }
                    }
                }
            }
        }
        grid_bar(sense);
    }
}

// ---------------------------------------------------------------------------
// Weight packing
// ---------------------------------------------------------------------------
__global__ void pack_w(const float* __restrict__ src, int ld, int coff,
                       __nv_bfloat16* __restrict__ hi, __nv_bfloat16* __restrict__ lo,
                       int n, int K) {
    int i = blockIdx.x * 256 + threadIdx.x;
    if (i < n) {
        int r = i / K, k = i - r * K;
        float v = src[(size_t)r * ld + coff + k];
        __nv_bfloat16 h = __float2bfloat16(v);
        hi[i] = h;
        lo[i] = __float2bfloat16(v - __bfloat162float(h));
    }
}

__global__ void pack_wiht(const float* __restrict__ Wih) {
    int idx = blockIdx.x * blockDim.x + threadIdx.x;
    if (idx < 1536 * 64) {
        int row = idx / 64, k = idx % 64;
        g_wiht[k * 1536 + row] = Wih[idx];
    }
}

// ---------------------------------------------------------------------------
// Host
// ---------------------------------------------------------------------------
extern "C" void kernel_launch(void* const* d_in, const int* in_sizes, int n_in,
                              void* d_out, int out_size) {
    const float* obs     = (const float*)d_in[0];
    const float* eps     = (const float*)d_in[1];
    const float* enc_W0  = (const float*)d_in[2];
    const float* enc_b0  = (const float*)d_in[3];
    const float* enc_W1  = (const float*)d_in[4];
    const float* enc_b1  = (const float*)d_in[5];
    const float* enc_W2  = (const float*)d_in[6];
    const float* enc_b2  = (const float*)d_in[7];
    const float* pri_W0  = (const float*)d_in[8];
    const float* pri_b0  = (const float*)d_in[9];
    const float* pri_W1  = (const float*)d_in[10];
    const float* pri_b1  = (const float*)d_in[11];
    const float* pri_W2  = (const float*)d_in[12];
    const float* pri_b2  = (const float*)d_in[13];
    const float* pos_W0  = (const float*)d_in[14];
    const float* pos_b0  = (const float*)d_in[15];
    const float* pos_W1  = (const float*)d_in[16];
    const float* pos_b1  = (const float*)d_in[17];
    const float* pos_W2  = (const float*)d_in[18];
    const float* pos_b2  = (const float*)d_in[19];
    const float* dec_W0  = (const float*)d_in[20];
    const float* dec_b0  = (const float*)d_in[21];
    const float* dec_W1  = (const float*)d_in[22];
    const float* dec_b1  = (const float*)d_in[23];
    const float* dec_W2  = (const float*)d_in[24];
    const float* dec_b2  = (const float*)d_in[25];
    const float* gru_Wih = (const float*)d_in[26];
    const float* gru_bih = (const float*)d_in[27];
    const float* gru_Whh = (const float*)d_in[28];
    const float* gru_bhh = (const float*)d_in[29];
    (void)in_sizes; (void)n_in; (void)out_size;

    __nv_bfloat16 *bufA_hi, *bufA_lo, *bufB_hi, *bufB_lo, *z_hi, *z_lo;
    __nv_bfloat16 *whi, *wlo, *h_hi, *h_lo;
    float *posc, *h;
    cudaGetSymbolAddress((void**)&bufA_hi, g_bufA_hi);
    cudaGetSymbolAddress((void**)&bufA_lo, g_bufA_lo);
    cudaGetSymbolAddress((void**)&bufB_hi, g_bufB_hi);
    cudaGetSymbolAddress((void**)&bufB_lo, g_bufB_lo);
    cudaGetSymbolAddress((void**)&z_hi,    g_z_hi);
    cudaGetSymbolAddress((void**)&z_lo,    g_z_lo);
    cudaGetSymbolAddress((void**)&posc,    g_posc);
    cudaGetSymbolAddress((void**)&h,       g_h);
    cudaGetSymbolAddress((void**)&h_hi,    g_h_hi);
    cudaGetSymbolAddress((void**)&h_lo,    g_h_lo);
    cudaGetSymbolAddress((void**)&whi,     g_whi);
    cudaGetSymbolAddress((void**)&wlo,     g_wlo);

    float* recons = (float*)d_out;
    float* kls    = recons + (size_t)BT_ * OBS_;
    float* mu     = kls + BT_;

    // init + packing
    cudaMemsetAsync(h,    0, (size_t)B_ * 512 * sizeof(float));
    cudaMemsetAsync(h_hi, 0, (size_t)B_ * 512 * sizeof(__nv_bfloat16));
    cudaMemsetAsync(h_lo, 0, (size_t)B_ * 512 * sizeof(__nv_bfloat16));
    pack_wiht<<<(1536 * 64 + 255) / 256, 256>>>(gru_Wih);

    auto pk = [&](const float* src, int ld, int coff, int off, int rows, int K) {
        int n = rows * K;
        pack_w<<<(n + 255) / 256, 256>>>(src, ld, coff, whi + off, wlo + off, n, K);
    };
    pk(enc_W0, 256, 0,    OFF_encW0,  512, 256);
    pk(enc_W1, 512, 0,    OFF_encW1,  512, 512);
    pk(enc_W2, 512, 0,    OFF_encW2,  512, 512);
    pk(pos_W0, 1024, 512, OFF_posW0e, 512, 512);
    pk(pos_W0, 1024, 0,   OFF_posW0h, 512, 512);
    pk(pri_W0, 512, 0,    OFF_priW0,  512, 512);
    pk(gru_Whh, 512, 0,   OFF_gruWhh, 1536, 512);
    pk(pri_W1, 512, 0,    OFF_priW1,  512, 512);
    pk(pos_W1, 512, 0,    OFF_posW1,  512, 512);
    pk(pri_W2, 512, 0,    OFF_priW2,  128, 512);
    pk(pos_W2, 512, 0,    OFF_posW2,  128, 512);
    pk(dec_W0, 64, 0,     OFF_decW0,  512, 64);
    pk(dec_W1, 512, 0,    OFF_decW1,  512, 512);
    pk(dec_W2, 512, 0,    OFF_decW2,  256, 512);

    // ---- Encoder chain (parallel over B*T) ----
    gemm_big<false><<<dim3(4, BT_ / 128), 256>>>(
        obs, nullptr, nullptr, 256, whi + OFF_encW0, wlo + OFF_encW0, 256,
        enc_b0, 1, 1, nullptr, bufA_hi, bufA_lo, 512);
    gemm_big<true><<<dim3(4, BT_ / 128), 256>>>(
        nullptr, bufA_hi, bufA_lo, 512, whi + OFF_encW1, wlo + OFF_encW1, 512,
        enc_b1, 1, 1, nullptr, bufB_hi, bufB_lo, 512);
    gemm_big<true><<<dim3(4, BT_ / 128), 256>>>(
        nullptr, bufB_hi, bufB_lo, 512, whi + OFF_encW2, wlo + OFF_encW2, 512,
        enc_b2, 0, 1, nullptr, bufA_hi, bufA_lo, 512);
    gemm_big<true><<<dim3(4, BT_ / 128), 256>>>(
        nullptr, bufA_hi, bufA_lo, 512, whi + OFF_posW0e, wlo + OFF_posW0e, 512,
        pos_b0, 0, 0, posc, nullptr, nullptr, 512);

    // ---- Persistent sequential loop ----
    SeqArgs sa;
    sa.eps = eps; sa.bih = gru_bih;
    sa.pri_b0 = pri_b0; sa.bhh = gru_bhh;
    sa.pri_b1 = pri_b1; sa.pos_b1 = pos_b1;
    sa.pri_b2 = pri_b2; sa.pos_b2 = pos_b2;
    sa.kls = kls; sa.mu = mu;
    seq_kernel<<<SEQ_GRID, 256>>>(sa);

    // ---- Decoder chain (parallel over B*T) ----
    gemm_big<true><<<dim3(4, BT_ / 128), 256>>>(
        nullptr, z_hi, z_lo, 64, whi + OFF_decW0, wlo + OFF_decW0, 64,
        dec_b0, 1, 1, nullptr, bufA_hi, bufA_lo, 512);
    gemm_big<true><<<dim3(4, BT_ / 128), 256>>>(
        nullptr, bufA_hi, bufA_lo, 512, whi + OFF_decW1, wlo + OFF_decW1, 512,
        dec_b1, 1, 1, nullptr, bufB_hi, bufB_lo, 512);
    gemm_big<true><<<dim3(2, BT_ / 128), 256>>>(
        nullptr, bufB_hi, bufB_lo, 512, whi + OFF_decW2, wlo + OFF_decW2, 512,
        dec_b2, 0, 0, recons, nullptr, nullptr, 256);
}

// round 6
// speedup vs baseline: 1.0735x; 1.0735x over previous
#include <cuda_runtime.h>
#include <cuda_bf16.h>
#include <cstdint>

// Problem constants
#define B_   1024
#define T_   128
#define OBS_ 256
#define LAT_ 64
#define BT_  (B_ * T_)   // 131072
#define SROW 40          // padded smem row (bf16 elems): conflict-free LDSM
#define STG  40960       // bytes per smem stage (4 arrays x 128 x SROW x 2B)
#define SMEM_DYN (2 * STG)

// ---------------------------------------------------------------------------
// Static device scratch
// ---------------------------------------------------------------------------
__device__ __nv_bfloat16 g_bufA_hi[(size_t)BT_ * 512];
__device__ __nv_bfloat16 g_bufA_lo[(size_t)BT_ * 512];
__device__ __nv_bfloat16 g_bufB_hi[(size_t)BT_ * 512];
__device__ __nv_bfloat16 g_bufB_lo[(size_t)BT_ * 512];
__device__ float         g_posc[(size_t)BT_ * 512];
__device__ __nv_bfloat16 g_z_hi[(size_t)BT_ * 64];
__device__ __nv_bfloat16 g_z_lo[(size_t)BT_ * 64];
__device__ __nv_bfloat16 g_act_hi[(size_t)B_ * 1024];
__device__ __nv_bfloat16 g_act_lo[(size_t)B_ * 1024];
__device__ __nv_bfloat16 g_a1_hi[(size_t)B_ * 1024];
__device__ __nv_bfloat16 g_a1_lo[(size_t)B_ * 1024];
__device__ float         g_gh[(size_t)B_ * 1536];
__device__ float         g_out2[(size_t)B_ * 256];
__device__ float         g_h[(size_t)B_ * 512];
__device__ __nv_bfloat16 g_h_hi[(size_t)B_ * 512];
__device__ __nv_bfloat16 g_h_lo[(size_t)B_ * 512];
__device__ float         g_wiht[64 * 1536];

enum : int {
    OFF_encW0  = 0,
    OFF_encW1  = OFF_encW0  + 512 * 256,
    OFF_encW2  = OFF_encW1  + 512 * 512,
    OFF_posW0e = OFF_encW2  + 512 * 512,
    OFF_posW0h = OFF_posW0e + 512 * 512,
    OFF_priW0  = OFF_posW0h + 512 * 512,
    OFF_gruWhh = OFF_priW0  + 512 * 512,
    OFF_priW1  = OFF_gruWhh + 1536 * 512,
    OFF_posW1  = OFF_priW1  + 512 * 512,
    OFF_priW2  = OFF_posW1  + 512 * 512,
    OFF_posW2  = OFF_priW2  + 128 * 512,
    OFF_decW0  = OFF_posW2  + 128 * 512,
    OFF_decW1  = OFF_decW0  + 512 * 64,
    OFF_decW2  = OFF_decW1  + 512 * 512,
    WTOT       = OFF_decW2  + 256 * 512
};
__device__ __nv_bfloat16 g_whi[WTOT];
__device__ __nv_bfloat16 g_wlo[WTOT];

__device__ __forceinline__ float eluf(float x) { return x > 0.f ? x : expm1f(x); }

__device__ __forceinline__ uint32_t smem_u32(const void* p) {
    uint32_t a;
    asm("{ .reg .u64 t; cvta.to.shared.u64 t, %1; cvt.u32.u64 %0, t; }" : "=r"(a) : "l"(p));
    return a;
}
__device__ __forceinline__ void cpasync16(uint32_t saddr, const void* gptr) {
    asm volatile("cp.async.cg.shared.global [%0], [%1], 16;" :: "r"(saddr), "l"(gptr));
}
__device__ __forceinline__ void cp_commit() {
    asm volatile("cp.async.commit_group;" ::: "memory");
}
__device__ __forceinline__ void ldsm4(uint32_t* r, uint32_t addr) {
    asm volatile("ldmatrix.sync.aligned.m8n8.x4.shared.b16 {%0,%1,%2,%3}, [%4];"
                 : "=r"(r[0]), "=r"(r[1]), "=r"(r[2]), "=r"(r[3]) : "r"(addr));
}
__device__ __forceinline__ void mma_bf16(float* c, const uint32_t* a, uint32_t b0, uint32_t b1) {
    asm volatile(
        "mma.sync.aligned.m16n8k16.row.col.f32.bf16.bf16.f32 "
        "{%0,%1,%2,%3}, {%4,%5,%6,%7}, {%8,%9}, {%0,%1,%2,%3};"
        : "+f"(c[0]), "+f"(c[1]), "+f"(c[2]), "+f"(c[3])
        : "r"(a[0]), "r"(a[1]), "r"(a[2]), "r"(a[3]), "r"(b0), "r"(b1));
}

// ---------------------------------------------------------------------------
// Grouped GEMM descriptor (up to 3 groups; tiles never straddle groups)
// ---------------------------------------------------------------------------
struct GemmTC {
    const float*         Af[3];
    const __nv_bfloat16* Ahi[3];
    const __nv_bfloat16* Alo[3];
    int                  lda[3];
    const __nv_bfloat16* Whi[3];
    const __nv_bfloat16* Wlo[3];
    const float*         bias[3];
    const float*         add[3];
    long                 ldadd[3];
    float*               Cf[3];
    __nv_bfloat16*       Chi[3];
    __nv_bfloat16*       Clo[3];
    int                  ldc[3];
    int                  act[3];
    int                  mode[3];   // 0 = fp32 out, 1 = bf16 pairs out
    int                  n_off[4];
    int K, ng;
};

template <bool APAIRS>
__global__ void __launch_bounds__(256, 1) gemm_tc(GemmTC d) {
    extern __shared__ char smem[];
    const uint32_t sb = smem_u32(smem);

    const int tid = threadIdx.x;
    const int wid = tid >> 5;
    const int lane = tid & 31;
    const int warp_m = wid & 1;
    const int warp_n = wid >> 1;

    const int n0 = blockIdx.x * 128;
    const int m0 = blockIdx.y * 128;
    int g = 0;
    while (g + 1 < d.ng && n0 >= d.n_off[g + 1]) g++;
    const int nl0 = n0 - d.n_off[g];
    const int K = d.K;
    const int NC = K >> 5;

    const float*         Af  = APAIRS ? nullptr : d.Af[g];
    const __nv_bfloat16* Ahi = d.Ahi[g];
    const __nv_bfloat16* Alo = d.Alo[g];
    const int lda = d.lda[g];
    const __nv_bfloat16* Whi = d.Whi[g] + (size_t)nl0 * K;
    const __nv_bfloat16* Wlo = d.Wlo[g] + (size_t)nl0 * K;

    float acc[4][4][4];
#pragma unroll
    for (int i = 0; i < 4; i++)
#pragma unroll
        for (int j = 0; j < 4; j++)
#pragma unroll
            for (int q = 0; q < 4; q++) acc[i][j][q] = 0.f;

    // ---- async issue helpers ----
    auto issueW = [&](int kc) {
        const uint32_t st = sb + (kc & 1) * STG;
        const int k0 = kc << 5;
#pragma unroll
        for (int i = 0; i < 2; i++) {
            const int idx = tid + i * 256;
            const int row = idx >> 2, ch = idx & 3;
            const uint32_t so = st + 20480 + row * 80 + ch * 16;
            cpasync16(so,         Whi + (size_t)row * K + k0 + ch * 8);
            cpasync16(so + 10240, Wlo + (size_t)row * K + k0 + ch * 8);
        }
    };
    auto issueA_pairs = [&](int kc) {
        const uint32_t st = sb + (kc & 1) * STG;
        const int k0 = kc << 5;
#pragma unroll
        for (int i = 0; i < 2; i++) {
            const int idx = tid + i * 256;
            const int row = idx >> 2, ch = idx & 3;
            const uint32_t so = st + row * 80 + ch * 16;
            cpasync16(so,         Ahi + (size_t)(m0 + row) * lda + k0 + ch * 8);
            cpasync16(so + 10240, Alo + (size_t)(m0 + row) * lda + k0 + ch * 8);
        }
    };

    float av[16];
    auto ldgA = [&](int kc) {
        const int k0 = kc << 5;
#pragma unroll
        for (int i = 0; i < 4; i++) {
            const int idx = tid + i * 256;
            const int row = idx >> 3, col = (idx & 7) * 4;
            const float4 v = *reinterpret_cast<const float4*>(
                Af + (size_t)(m0 + row) * lda + k0 + col);
            av[i * 4 + 0] = v.x; av[i * 4 + 1] = v.y;
            av[i * 4 + 2] = v.z; av[i * 4 + 3] = v.w;
        }
    };
    auto storeA = [&](int kc) {
        char* stp = smem + (kc & 1) * STG;
#pragma unroll
        for (int i = 0; i < 4; i++) {
            const int idx = tid + i * 256;
            const int row = idx >> 3, col = (idx & 7) * 4;
            float x0 = av[i * 4 + 0], x1 = av[i * 4 + 1];
            float x2 = av[i * 4 + 2], x3 = av[i * 4 + 3];
            __nv_bfloat162 h01 = __floats2bfloat162_rn(x0, x1);
            __nv_bfloat162 h23 = __floats2bfloat162_rn(x2, x3);
            __nv_bfloat162 l01 = __floats2bfloat162_rn(x0 - __bfloat162float(h01.x),
                                                       x1 - __bfloat162float(h01.y));
            __nv_bfloat162 l23 = __floats2bfloat162_rn(x2 - __bfloat162float(h23.x),
                                                       x3 - __bfloat162float(h23.y));
            const int bo = row * 80 + col * 2;
            *reinterpret_cast<uint2*>(stp + bo) =
                make_uint2(*reinterpret_cast<uint32_t*>(&h01), *reinterpret_cast<uint32_t*>(&h23));
            *reinterpret_cast<uint2*>(stp + 10240 + bo) =
                make_uint2(*reinterpret_cast<uint32_t*>(&l01), *reinterpret_cast<uint32_t*>(&l23));
        }
    };

    // ---- fragment address bases ----
    const int lane15 = lane & 15;
    const int koff = (lane >> 4) << 3;
    const uint32_t arow = (uint32_t)(warp_m * 64 + lane15);
    const uint32_t brow = (uint32_t)(warp_n * 32 + lane15);

    auto compute = [&](int kc) {
        const uint32_t stb = sb + (kc & 1) * STG;
#pragma unroll
        for (int ks = 0; ks < 32; ks += 16) {
            const uint32_t acol = (uint32_t)(ks + koff) * 2;
            uint32_t ah[4][4], al[4][4];
#pragma unroll
            for (int mf = 0; mf < 4; mf++) {
                const uint32_t ad = stb + (arow + mf * 16) * 80 + acol;
                ldsm4(ah[mf], ad);
                ldsm4(al[mf], ad + 10240);
            }
            uint32_t bh[2][4], bl[2][4];
#pragma unroll
            for (int nfp = 0; nfp < 2; nfp++) {
                const uint32_t bd = stb + 20480 + (brow + nfp * 16) * 80 + acol;
                ldsm4(bh[nfp], bd);
                ldsm4(bl[nfp], bd + 10240);
            }
#pragma unroll
            for (int nfp = 0; nfp < 2; nfp++)
#pragma unroll
                for (int j = 0; j < 2; j++) {
                    const int nf = nfp * 2 + j;
                    const uint32_t bh0 = bh[nfp][j], bh1 = bh[nfp][2 + j];
                    const uint32_t bl0 = bl[nfp][j], bl1 = bl[nfp][2 + j];
#pragma unroll
                    for (int mf = 0; mf < 4; mf++) {
                        mma_bf16(acc[mf][nf], ah[mf], bh0, bh1);
                        mma_bf16(acc[mf][nf], ah[mf], bl0, bl1);
                        mma_bf16(acc[mf][nf], al[mf], bh0, bh1);
                    }
                }
        }
    };

    // ---- pipeline ----
    if (APAIRS) {
        issueA_pairs(0); issueW(0); cp_commit();
        for (int kc = 0; kc < NC; kc++) {
            if (kc + 1 < NC) { issueA_pairs(kc + 1); issueW(kc + 1); cp_commit(); }
            if (kc + 1 < NC) asm volatile("cp.async.wait_group 1;" ::: "memory");
            else             asm volatile("cp.async.wait_group 0;" ::: "memory");
            __syncthreads();
            compute(kc);
            __syncthreads();
        }
    } else {
        ldgA(0);
        issueW(0); cp_commit();
        for (int kc = 0; kc < NC; kc++) {
            storeA(kc);
            if (kc + 1 < NC) { issueW(kc + 1); cp_commit(); }
            if (kc + 1 < NC) asm volatile("cp.async.wait_group 1;" ::: "memory");
            else             asm volatile("cp.async.wait_group 0;" ::: "memory");
            __syncthreads();
            if (kc + 1 < NC) ldgA(kc + 1);
            compute(kc);
            __syncthreads();
        }
    }

    // ---- epilogue ----
    const float* bias = d.bias[g];
    const float* add  = d.add[g];
    const long ldadd  = d.ldadd[g];
    const int act     = d.act[g];
    const int mode    = d.mode[g];
    const int ldc     = d.ldc[g];
    float* Cf         = d.Cf[g];
    __nv_bfloat16* Chi = d.Chi[g];
    __nv_bfloat16* Clo = d.Clo[g];

    const int gid = lane >> 2;
    const int tig = lane & 3;
#pragma unroll
    for (int mf = 0; mf < 4; mf++) {
        const int r0 = m0 + warp_m * 64 + mf * 16 + gid;
#pragma unroll
        for (int nf = 0; nf < 4; nf++) {
            const int coll = nl0 + warp_n * 32 + nf * 8 + tig * 2;
            float v0 = acc[mf][nf][0], v1 = acc[mf][nf][1];
            float v2 = acc[mf][nf][2], v3 = acc[mf][nf][3];
            if (bias) {
                const float b0v = bias[coll], b1v = bias[coll + 1];
                v0 += b0v; v1 += b1v; v2 += b0v; v3 += b1v;
            }
            if (add) {
                const float2 a0 = *reinterpret_cast<const float2*>(add + (size_t)r0 * ldadd + coll);
                const float2 a1 = *reinterpret_cast<const float2*>(add + (size_t)(r0 + 8) * ldadd + coll);
                v0 += a0.x; v1 += a0.y; v2 += a1.x; v3 += a1.y;
            }
            if (act) { v0 = eluf(v0); v1 = eluf(v1); v2 = eluf(v2); v3 = eluf(v3); }
            if (mode == 0) {
                *reinterpret_cast<float2*>(Cf + (size_t)r0 * ldc + coll)       = make_float2(v0, v1);
                *reinterpret_cast<float2*>(Cf + (size_t)(r0 + 8) * ldc + coll) = make_float2(v2, v3);
            } else {
                __nv_bfloat162 h0 = __floats2bfloat162_rn(v0, v1);
                __nv_bfloat162 l0 = __floats2bfloat162_rn(v0 - __bfloat162float(h0.x),
                                                          v1 - __bfloat162float(h0.y));
                __nv_bfloat162 h1 = __floats2bfloat162_rn(v2, v3);
                __nv_bfloat162 l1 = __floats2bfloat162_rn(v2 - __bfloat162float(h1.x),
                                                          v3 - __bfloat162float(h1.y));
                *reinterpret_cast<uint32_t*>(Chi + (size_t)r0 * ldc + coll)       = *reinterpret_cast<uint32_t*>(&h0);
                *reinterpret_cast<uint32_t*>(Clo + (size_t)r0 * ldc + coll)       = *reinterpret_cast<uint32_t*>(&l0);
                *reinterpret_cast<uint32_t*>(Chi + (size_t)(r0 + 8) * ldc + coll) = *reinterpret_cast<uint32_t*>(&h1);
                *reinterpret_cast<uint32_t*>(Clo + (size_t)(r0 + 8) * ldc + coll) = *reinterpret_cast<uint32_t*>(&l1);
            }
        }
    }
}

// ---------------------------------------------------------------------------
// Single init kernel: pack all weights (hi/lo), Wih^T, zero h (one launch)
// ---------------------------------------------------------------------------
struct PackArgs {
    const float* src[14];
    int ld[14];
    int coff[14];
    const float* wih;
};
__constant__ int c_seg_off[15] = {
    OFF_encW0, OFF_encW1, OFF_encW2, OFF_posW0e, OFF_posW0h, OFF_priW0,
    OFF_gruWhh, OFF_priW1, OFF_posW1, OFF_priW2, OFF_posW2, OFF_decW0,
    OFF_decW1, OFF_decW2, WTOT
};
__constant__ int c_seg_K[14] = {
    256, 512, 512, 512, 512, 512, 512, 512, 512, 512, 512, 64, 512, 512
};

#define PACK_EXTRA (64 * 1536 + B_ * 512)
__global__ void pack_all(PackArgs a) {
    const int i = blockIdx.x * 256 + threadIdx.x;
    if (i < WTOT) {
        int s = 0;
        while (s + 1 < 14 && i >= c_seg_off[s + 1]) s++;
        const int li = i - c_seg_off[s];
        const int K = c_seg_K[s];
        const int r = li / K, k = li - r * K;
        const float v = a.src[s][(size_t)r * a.ld[s] + a.coff[s] + k];
        const __nv_bfloat16 h = __float2bfloat16(v);
        g_whi[i] = h;
        g_wlo[i] = __float2bfloat16(v - __bfloat162float(h));
    } else if (i < WTOT + 64 * 1536) {
        const int li = i - WTOT;
        const int row = li / 64, k = li - row * 64;
        g_wiht[k * 1536 + row] = a.wih[li];
    } else if (i < WTOT + 64 * 1536 + B_ * 512) {
        const int li = i - WTOT - 64 * 1536;
        g_h[li] = 0.f;
        g_h_hi[li] = __float2bfloat16(0.f);
        g_h_lo[li] = __float2bfloat16(0.f);
    }
}

// ---------------------------------------------------------------------------
// Fused latent + GRU kernel (per timestep)
// ---------------------------------------------------------------------------
#define TMB 4
__global__ void gru_latent_kernel(const float* __restrict__ eps,
                                  const float* __restrict__ bih,
                                  float* __restrict__ kls_out,
                                  float* __restrict__ mu_out,
                                  int t) {
    __shared__ float zs[TMB][64];
    __shared__ float klw[TMB * 2];

    const int m0 = blockIdx.x * TMB;
    const int tid = threadIdx.x;

    if (tid < TMB * 64) {
        const int r = tid >> 6, k = tid & 63;
        const int m = m0 + r;
        const float* o = g_out2 + (size_t)m * 256;
        float mu_p = o[k], ls_p = o[64 + k], mu_q = o[128 + k], ls_q = o[192 + k];
        float e = eps[((size_t)m * T_ + t) * 64 + k];
        float zl = fmaf(expf(ls_q), e, mu_q);
        zs[r][k] = zl;
        const __nv_bfloat16 zh = __float2bfloat16(zl);
        g_z_hi[((size_t)m * T_ + t) * 64 + k] = zh;
        g_z_lo[((size_t)m * T_ + t) * 64 + k] = __float2bfloat16(zl - __bfloat162float(zh));
        mu_out[((size_t)m * T_ + t) * 64 + k] = mu_q;
        float dm = mu_q - mu_p;
        float klv = ls_p - ls_q + (expf(2.f * ls_q) + dm * dm) / (2.f * expf(2.f * ls_p)) - 0.5f;
#pragma unroll
        for (int off = 16; off > 0; off >>= 1)
            klv += __shfl_down_sync(0xffffffffu, klv, off);
        if ((tid & 31) == 0) klw[tid >> 5] = klv;
    }
    __syncthreads();
    if (tid < TMB) kls_out[(size_t)(m0 + tid) * T_ + t] = klw[2 * tid] + klw[2 * tid + 1];

    const int j = tid;
    float ar[TMB], az[TMB], an[TMB];
#pragma unroll
    for (int r = 0; r < TMB; r++) { ar[r] = 0.f; az[r] = 0.f; an[r] = 0.f; }

#pragma unroll 8
    for (int k = 0; k < 64; k++) {
        float wr = g_wiht[k * 1536 + j];
        float wz = g_wiht[k * 1536 + 512 + j];
        float wn = g_wiht[k * 1536 + 1024 + j];
#pragma unroll
        for (int r = 0; r < TMB; r++) {
            float zk = zs[r][k];
            ar[r] = fmaf(zk, wr, ar[r]);
            az[r] = fmaf(zk, wz, az[r]);
            an[r] = fmaf(zk, wn, an[r]);
        }
    }

    const float br = bih[j], bz = bih[512 + j], bn = bih[1024 + j];
#pragma unroll
    for (int r = 0; r < TMB; r++) {
        const int m = m0 + r;
        const float* gr = g_gh + (size_t)m * 1536;
        float ghr = gr[j], ghz = gr[512 + j], ghn = gr[1024 + j];
        float rg = 1.f / (1.f + expf(-(ar[r] + br + ghr)));
        float zg = 1.f / (1.f + expf(-(az[r] + bz + ghz)));
        float ng = tanhf(an[r] + bn + rg * ghn);
        float hv = g_h[(size_t)m * 512 + j];
        float hn = (1.f - zg) * ng + zg * hv;
        g_h[(size_t)m * 512 + j] = hn;
        const __nv_bfloat16 hh = __float2bfloat16(hn);
        g_h_hi[(size_t)m * 512 + j] = hh;
        g_h_lo[(size_t)m * 512 + j] = __float2bfloat16(hn - __bfloat162float(hh));
    }
}

// ---------------------------------------------------------------------------
// Host helpers
// ---------------------------------------------------------------------------
static inline GemmTC make_desc(int K) {
    GemmTC d{};
    d.K = K; d.ng = 0; d.n_off[0] = 0;
    return d;
}
static inline void add_group(GemmTC& d, int nsub,
                             const float* Af, const __nv_bfloat16* Ahi, const __nv_bfloat16* Alo, int lda,
                             const __nv_bfloat16* Whi, const __nv_bfloat16* Wlo,
                             const float* bias, const float* add, long ldadd, int act,
                             int mode, float* Cf, __nv_bfloat16* Chi, __nv_bfloat16* Clo, int ldc) {
    const int g = d.ng;
    d.Af[g] = Af; d.Ahi[g] = Ahi; d.Alo[g] = Alo; d.lda[g] = lda;
    d.Whi[g] = Whi; d.Wlo[g] = Wlo;
    d.bias[g] = bias; d.add[g] = add; d.ldadd[g] = ldadd;
    d.act[g] = act; d.mode[g] = mode;
    d.Cf[g] = Cf; d.Chi[g] = Chi; d.Clo[g] = Clo; d.ldc[g] = ldc;
    d.n_off[g + 1] = d.n_off[g] + nsub;
    d.ng = g + 1;
}

extern "C" void kernel_launch(void* const* d_in, const int* in_sizes, int n_in,
                              void* d_out, int out_size) {
    const float* obs     = (const float*)d_in[0];
    const float* eps     = (const float*)d_in[1];
    const float* enc_W0  = (const float*)d_in[2];
    const float* enc_b0  = (const float*)d_in[3];
    const float* enc_W1  = (const float*)d_in[4];
    const float* enc_b1  = (const float*)d_in[5];
    const float* enc_W2  = (const float*)d_in[6];
    const float* enc_b2  = (const float*)d_in[7];
    const float* pri_W0  = (const float*)d_in[8];
    const float* pri_b0  = (const float*)d_in[9];
    const float* pri_W1  = (const float*)d_in[10];
    const float* pri_b1  = (const float*)d_in[11];
    const float* pri_W2  = (const float*)d_in[12];
    const float* pri_b2  = (const float*)d_in[13];
    const float* pos_W0  = (const float*)d_in[14];
    const float* pos_b0  = (const float*)d_in[15];
    const float* pos_W1  = (const float*)d_in[16];
    const float* pos_b1  = (const float*)d_in[17];
    const float* pos_W2  = (const float*)d_in[18];
    const float* pos_b2  = (const float*)d_in[19];
    const float* dec_W0  = (const float*)d_in[20];
    const float* dec_b0  = (const float*)d_in[21];
    const float* dec_W1  = (const float*)d_in[22];
    const float* dec_b1  = (const float*)d_in[23];
    const float* dec_W2  = (const float*)d_in[24];
    const float* dec_b2  = (const float*)d_in[25];
    const float* gru_Wih = (const float*)d_in[26];
    const float* gru_bih = (const float*)d_in[27];
    const float* gru_Whh = (const float*)d_in[28];
    const float* gru_bhh = (const float*)d_in[29];
    (void)in_sizes; (void)n_in; (void)out_size;

    __nv_bfloat16 *bufA_hi, *bufA_lo, *bufB_hi, *bufB_lo, *z_hi, *z_lo;
    __nv_bfloat16 *whi, *wlo, *act_hi, *act_lo, *a1_hi, *a1_lo, *h_hi, *h_lo;
    float *posc, *gh, *out2;
    cudaGetSymbolAddress((void**)&bufA_hi, g_bufA_hi);
    cudaGetSymbolAddress((void**)&bufA_lo, g_bufA_lo);
    cudaGetSymbolAddress((void**)&bufB_hi, g_bufB_hi);
    cudaGetSymbolAddress((void**)&bufB_lo, g_bufB_lo);
    cudaGetSymbolAddress((void**)&z_hi,    g_z_hi);
    cudaGetSymbolAddress((void**)&z_lo,    g_z_lo);
    cudaGetSymbolAddress((void**)&posc,    g_posc);
    cudaGetSymbolAddress((void**)&whi,     g_whi);
    cudaGetSymbolAddress((void**)&wlo,     g_wlo);
    cudaGetSymbolAddress((void**)&act_hi,  g_act_hi);
    cudaGetSymbolAddress((void**)&act_lo,  g_act_lo);
    cudaGetSymbolAddress((void**)&a1_hi,   g_a1_hi);
    cudaGetSymbolAddress((void**)&a1_lo,   g_a1_lo);
    cudaGetSymbolAddress((void**)&h_hi,    g_h_hi);
    cudaGetSymbolAddress((void**)&h_lo,    g_h_lo);
    cudaGetSymbolAddress((void**)&gh,      g_gh);
    cudaGetSymbolAddress((void**)&out2,    g_out2);

    cudaFuncSetAttribute(gemm_tc<true>,  cudaFuncAttributeMaxDynamicSharedMemorySize, SMEM_DYN);
    cudaFuncSetAttribute(gemm_tc<false>, cudaFuncAttributeMaxDynamicSharedMemorySize, SMEM_DYN);

    float* recons = (float*)d_out;
    float* kls    = recons + (size_t)BT_ * OBS_;
    float* mu     = kls + BT_;

    // ---- single init/pack launch ----
    PackArgs pa;
    const float* srcs[14] = { enc_W0, enc_W1, enc_W2, pos_W0, pos_W0, pri_W0, gru_Whh,
                              pri_W1, pos_W1, pri_W2, pos_W2, dec_W0, dec_W1, dec_W2 };
    const int lds[14]   = { 256, 512, 512, 1024, 1024, 512, 512, 512, 512, 512, 512, 64, 512, 512 };
    const int coffs[14] = { 0, 0, 0, 512, 0, 0, 0, 0, 0, 0, 0, 0, 0, 0 };
    for (int i = 0; i < 14; i++) { pa.src[i] = srcs[i]; pa.ld[i] = lds[i]; pa.coff[i] = coffs[i]; }
    pa.wih = gru_Wih;
    pack_all<<<(WTOT + PACK_EXTRA + 255) / 256, 256>>>(pa);

    // ---- Encoder chain (parallel over B*T) ----
    {
        GemmTC d = make_desc(256);
        add_group(d, 512, obs, nullptr, nullptr, 256, whi + OFF_encW0, wlo + OFF_encW0,
                  enc_b0, nullptr, 0, 1, 1, nullptr, bufA_hi, bufA_lo, 512);
        gemm_tc<false><<<dim3(4, BT_ / 128), 256, SMEM_DYN>>>(d);
    }
    {
        GemmTC d = make_desc(512);
        add_group(d, 512, nullptr, bufA_hi, bufA_lo, 512, whi + OFF_encW1, wlo + OFF_encW1,
                  enc_b1, nullptr, 0, 1, 1, nullptr, bufB_hi, bufB_lo, 512);
        gemm_tc<true><<<dim3(4, BT_ / 128), 256, SMEM_DYN>>>(d);
    }
    {
        GemmTC d = make_desc(512);
        add_group(d, 512, nullptr, bufB_hi, bufB_lo, 512, whi + OFF_encW2, wlo + OFF_encW2,
                  enc_b2, nullptr, 0, 0, 1, nullptr, bufA_hi, bufA_lo, 512);
        gemm_tc<true><<<dim3(4, BT_ / 128), 256, SMEM_DYN>>>(d);
    }
    {
        GemmTC d = make_desc(512);
        add_group(d, 512, nullptr, bufA_hi, bufA_lo, 512, whi + OFF_posW0e, wlo + OFF_posW0e,
                  pos_b0, nullptr, 0, 0, 0, posc, nullptr, nullptr, 512);
        gemm_tc<true><<<dim3(4, BT_ / 128), 256, SMEM_DYN>>>(d);
    }

    // ---- Sequential recurrence ----
    for (int t = 0; t < T_; t++) {
        {
            GemmTC d = make_desc(512);
            add_group(d, 512, nullptr, h_hi, h_lo, 512, whi + OFF_priW0, wlo + OFF_priW0,
                      pri_b0, nullptr, 0, 1, 1, nullptr, act_hi, act_lo, 1024);
            add_group(d, 512, nullptr, h_hi, h_lo, 512, whi + OFF_posW0h, wlo + OFF_posW0h,
                      nullptr, posc + (size_t)t * 512, (long)T_ * 512, 1,
                      1, nullptr, act_hi + 512, act_lo + 512, 1024);
            add_group(d, 1536, nullptr, h_hi, h_lo, 512, whi + OFF_gruWhh, wlo + OFF_gruWhh,
                      gru_bhh, nullptr, 0, 0, 0, gh, nullptr, nullptr, 1536);
            gemm_tc<true><<<dim3(20, 8), 256, SMEM_DYN>>>(d);
        }
        {
            GemmTC d = make_desc(512);
            add_group(d, 512, nullptr, act_hi, act_lo, 1024, whi + OFF_priW1, wlo + OFF_priW1,
                      pri_b1, nullptr, 0, 1, 1, nullptr, a1_hi, a1_lo, 1024);
            add_group(d, 512, nullptr, act_hi + 512, act_lo + 512, 1024, whi + OFF_posW1, wlo + OFF_posW1,
                      pos_b1, nullptr, 0, 1, 1, nullptr, a1_hi + 512, a1_lo + 512, 1024);
            gemm_tc<true><<<dim3(8, 8), 256, SMEM_DYN>>>(d);
        }
        {
            GemmTC d = make_desc(512);
            add_group(d, 128, nullptr, a1_hi, a1_lo, 1024, whi + OFF_priW2, wlo + OFF_priW2,
                      pri_b2, nullptr, 0, 0, 0, out2, nullptr, nullptr, 256);
            add_group(d, 128, nullptr, a1_hi + 512, a1_lo + 512, 1024, whi + OFF_posW2, wlo + OFF_posW2,
                      pos_b2, nullptr, 0, 0, 0, out2 + 128, nullptr, nullptr, 256);
            gemm_tc<true><<<dim3(2, 8), 256, SMEM_DYN>>>(d);
        }
        gru_latent_kernel<<<B_ / TMB, 512>>>(eps, gru_bih, kls, mu, t);
    }

    // ---- Deferred decoder over all (B*T) rows ----
    {
        GemmTC d = make_desc(64);
        add_group(d, 512, nullptr, z_hi, z_lo, 64, whi + OFF_decW0, wlo + OFF_decW0,
                  dec_b0, nullptr, 0, 1, 1, nullptr, bufA_hi, bufA_lo, 512);
        gemm_tc<true><<<dim3(4, BT_ / 128), 256, SMEM_DYN>>>(d);
    }
    {
        GemmTC d = make_desc(512);
        add_group(d, 512, nullptr, bufA_hi, bufA_lo, 512, whi + OFF_decW1, wlo + OFF_decW1,
                  dec_b1, nullptr, 0, 1, 1, nullptr, bufB_hi, bufB_lo, 512);
        gemm_tc<true><<<dim3(4, BT_ / 128), 256, SMEM_DYN>>>(d);
    }
    {
        GemmTC d = make_desc(512);
        add_group(d, 256, nullptr, bufB_hi, bufB_lo, 512, whi + OFF_decW2, wlo + OFF_decW2,
                  dec_b2, nullptr, 0, 0, 0, recons, nullptr, nullptr, 256);
        gemm_tc<true><<<dim3(2, BT_ / 128), 256, SMEM_DYN>>>(d);
    }
}